// round 2
// baseline (speedup 1.0000x reference)
#include <cuda_runtime.h>

#define NB 64
#define NT 512
#define NI 512
#define NH 512
#define NG 2048      // 4*H
#define GRID_R 128   // recurrent persistent CTAs (<= 148 SMs -> co-resident)

// ---------------- device scratch (static: no allocs allowed) ----------------
__device__ float g_xg[(long long)NT * NG * NB];   // [t][gate][b]  (256 MB)
__device__ float g_hbuf[2][NH * NB];              // [k/4][b][4] packed layout
__device__ float g_bias[NG];
__device__ unsigned g_cnt;                        // monotonic ticket barrier

// ---------------- f32x2 packed-FMA helpers (Blackwell FFMA2) ----------------
__device__ __forceinline__ unsigned long long dup2(float x) {
    unsigned long long r;
    asm("mov.b64 %0, {%1,%1};" : "=l"(r) : "f"(x));
    return r;
}
__device__ __forceinline__ void fma2(unsigned long long& d,
                                     unsigned long long a,
                                     unsigned long long b) {
    asm("fma.rn.f32x2 %0, %1, %2, %0;" : "+l"(d) : "l"(a), "l"(b));
}
__device__ __forceinline__ float2 unpack2(unsigned long long v) {
    float lo, hi;
    asm("mov.b64 {%0,%1}, %2;" : "=f"(lo), "=f"(hi) : "l"(v));
    return make_float2(lo, hi);
}

// ---------------- init: repack h0, combine biases ----------------
__global__ void init_kernel(const float* __restrict__ h0,
                            const float* __restrict__ b_ih,
                            const float* __restrict__ b_hh) {
    int i = blockIdx.x * blockDim.x + threadIdx.x;
    if (i < NB * NH) {
        int b = i >> 9;
        int k = i & (NH - 1);
        g_hbuf[0][(k >> 2) * (NB * 4) + b * 4 + (k & 3)] = h0[i];
    }
    if (i < NG) g_bias[i] = b_ih[i] + b_hh[i];
}

// ---------------- xg GEMM: [32768,512] x [512,2048]^T -> g_xg[t][g][b] -------
#define STS_TILE(bufi)                                                         \
    do {                                                                       \
        As[bufi][ks + 0][r] = ra0.x; As[bufi][ks + 1][r] = ra0.y;              \
        As[bufi][ks + 2][r] = ra0.z; As[bufi][ks + 3][r] = ra0.w;              \
        As[bufi][ks + 4][r] = ra1.x; As[bufi][ks + 5][r] = ra1.y;              \
        As[bufi][ks + 6][r] = ra1.z; As[bufi][ks + 7][r] = ra1.w;              \
        Bs[bufi][ks + 0][r] = rb0.x; Bs[bufi][ks + 1][r] = rb0.y;              \
        Bs[bufi][ks + 2][r] = rb0.z; Bs[bufi][ks + 3][r] = rb0.w;              \
        Bs[bufi][ks + 4][r] = rb1.x; Bs[bufi][ks + 5][r] = rb1.y;              \
        Bs[bufi][ks + 6][r] = rb1.z; Bs[bufi][ks + 7][r] = rb1.w;              \
    } while (0)

__global__ __launch_bounds__(256, 2) void gemm_xg(const float* __restrict__ x,
                                                  const float* __restrict__ Wih) {
    __shared__ __align__(16) float As[2][16][132];
    __shared__ __align__(16) float Bs[2][16][132];

    const int tid = threadIdx.x;
    const int n0 = blockIdx.x * 128;   // gate-column block (16 blocks)
    const int m0 = blockIdx.y * 128;   // row block (256 blocks)
    const int tm = tid >> 4;
    const int tn = tid & 15;
    const int r  = tid >> 1;           // tile row this thread stages
    const int ks = (tid & 1) * 8;      // k-segment within 16

    const float* pa = x   + (long long)(m0 + r) * NI + ks;
    const float* pb = Wih + (long long)(n0 + r) * NI + ks;

    unsigned long long acc[8][4];
#pragma unroll
    for (int i = 0; i < 8; ++i)
#pragma unroll
        for (int j = 0; j < 4; ++j) acc[i][j] = 0ull;

    float4 ra0, ra1, rb0, rb1;
    ra0 = *(const float4*)(pa);
    ra1 = *(const float4*)(pa + 4);
    rb0 = *(const float4*)(pb);
    rb1 = *(const float4*)(pb + 4);
    STS_TILE(0);
    __syncthreads();

#pragma unroll 1
    for (int kt = 0; kt < 32; ++kt) {
        const int buf = kt & 1;
        if (kt < 31) {
            const float* qa = pa + (kt + 1) * 16;
            const float* qb = pb + (kt + 1) * 16;
            ra0 = *(const float4*)(qa);
            ra1 = *(const float4*)(qa + 4);
            rb0 = *(const float4*)(qb);
            rb1 = *(const float4*)(qb + 4);
        }
#pragma unroll
        for (int kk = 0; kk < 16; ++kk) {
            float4 a0 = *(const float4*)&As[buf][kk][tm * 8];
            float4 a1 = *(const float4*)&As[buf][kk][tm * 8 + 4];
            ulonglong2 b01 = *(const ulonglong2*)&Bs[buf][kk][tn * 8];
            ulonglong2 b23 = *(const ulonglong2*)&Bs[buf][kk][tn * 8 + 4];
            float av[8] = {a0.x, a0.y, a0.z, a0.w, a1.x, a1.y, a1.z, a1.w};
            unsigned long long bp[4] = {b01.x, b01.y, b23.x, b23.y};
#pragma unroll
            for (int i = 0; i < 8; ++i) {
                unsigned long long ad = dup2(av[i]);
                fma2(acc[i][0], ad, bp[0]);
                fma2(acc[i][1], ad, bp[1]);
                fma2(acc[i][2], ad, bp[2]);
                fma2(acc[i][3], ad, bp[3]);
            }
        }
        if (kt < 31) {
            const int nb = buf ^ 1;
            STS_TILE(nb);
            __syncthreads();
        }
    }

    // Epilogue: +bias, write to g_xg[t][g][b] (scatter along b/t; contiguous GEMM dims
    // were spent on coalescing the 512x-reread recurrent-side loads instead).
    float bias_[8];
#pragma unroll
    for (int j = 0; j < 8; ++j) bias_[j] = g_bias[n0 + tn * 8 + j];
#pragma unroll
    for (int i = 0; i < 8; ++i) {
        int m  = m0 + tm * 8 + i;
        int bb = m >> 9;           // batch
        int t  = m & (NT - 1);     // timestep
        float* orow = g_xg + ((long long)t * NG + (n0 + tn * 8)) * NB + bb;
#pragma unroll
        for (int j2 = 0; j2 < 4; ++j2) {
            float2 v = unpack2(acc[i][j2]);
            orow[(2 * j2) * NB]     = v.x + bias_[2 * j2];
            orow[(2 * j2 + 1) * NB] = v.y + bias_[2 * j2 + 1];
        }
    }
}

// ---------------- persistent recurrent kernel ----------------
// CTA k owns H-columns [4k, 4k+4). Thread (b = tid&63, c = tid>>6) computes all
// 4 gate pre-activations for element (b, 4k+c); c-state lives in a register.
__global__ __launch_bounds__(256, 1) void lstm_steps(const float* __restrict__ Whh,
                                                     const float* __restrict__ c0,
                                                     float* __restrict__ out,
                                                     int tail) {
    __shared__ __align__(16) float wsm[16 * 512];   // 16 W_hh rows (4 cols x 4 gates)
    __shared__ float hx[256];

    const int tid = threadIdx.x;
    const int b   = tid & 63;
    const int c   = tid >> 6;
    const int j0  = blockIdx.x * 4;
    const int j   = j0 + c;

    // Stage W_hh slice: smem row (q*4+cc) = Whh[q*NH + j0 + cc]
    for (int idx = tid * 4; idx < 16 * 512; idx += 256 * 4) {
        int rrow = idx >> 9;
        int k    = idx & 511;
        int q    = rrow >> 2;
        int cc   = rrow & 3;
        *(float4*)&wsm[rrow * 512 + k] =
            *(const float4*)&Whh[(long long)(q * NH + j0 + cc) * NH + k];
    }
    __syncthreads();

    float cs = c0[b * NH + j];
    int rd = 0;

    for (int t = 0; t < NT; ++t) {
        // prefetch this step's xg contributions (coalesced: b contiguous)
        const float* xgt = g_xg + (long long)t * NG * NB;
        float x0 = xgt[(0 * NH + j) * NB + b];
        float x1 = xgt[(1 * NH + j) * NB + b];
        float x2 = xgt[(2 * NH + j) * NB + b];
        float x3 = xgt[(3 * NH + j) * NB + b];

        const ulonglong2* hb = (const ulonglong2*)g_hbuf[rd];  // 16B = h[4k..4k+3]
        unsigned long long a00 = 0, a01 = 0, a10 = 0, a11 = 0;
        unsigned long long a20 = 0, a21 = 0, a30 = 0, a31 = 0;
#pragma unroll 8
        for (int k4 = 0; k4 < 128; ++k4) {
            ulonglong2 h2 = hb[k4 * 64 + b];                       // LDG.128, L2-hit
            ulonglong2 w0 = *(const ulonglong2*)&wsm[(0 * 4 + c) * 512 + k4 * 4];
            ulonglong2 w1 = *(const ulonglong2*)&wsm[(1 * 4 + c) * 512 + k4 * 4];
            ulonglong2 w2 = *(const ulonglong2*)&wsm[(2 * 4 + c) * 512 + k4 * 4];
            ulonglong2 w3 = *(const ulonglong2*)&wsm[(3 * 4 + c) * 512 + k4 * 4];
            fma2(a00, h2.x, w0.x); fma2(a01, h2.y, w0.y);
            fma2(a10, h2.x, w1.x); fma2(a11, h2.y, w1.y);
            fma2(a20, h2.x, w2.x); fma2(a21, h2.y, w2.y);
            fma2(a30, h2.x, w3.x); fma2(a31, h2.y, w3.y);
        }
        float2 u, v;
        u = unpack2(a00); v = unpack2(a01); float gi = (u.x + u.y) + (v.x + v.y) + x0;
        u = unpack2(a10); v = unpack2(a11); float gf = (u.x + u.y) + (v.x + v.y) + x1;
        u = unpack2(a20); v = unpack2(a21); float gg = (u.x + u.y) + (v.x + v.y) + x2;
        u = unpack2(a30); v = unpack2(a31); float go = (u.x + u.y) + (v.x + v.y) + x3;

        float iv = 1.f / (1.f + __expf(-gi));
        float fv = 1.f / (1.f + __expf(-gf));
        float gv = 2.f / (1.f + __expf(-2.f * gg)) - 1.f;
        float ov = 1.f / (1.f + __expf(-go));
        cs = fv * cs + iv * gv;
        float hn = ov * (2.f / (1.f + __expf(-2.f * cs)) - 1.f);

        // smem exchange -> coalesced float4 stores of h and output
        hx[c * 64 + b] = hn;
        __syncthreads();
        if (tid < 64) {
            float4 vv = make_float4(hx[tid], hx[64 + tid], hx[128 + tid], hx[192 + tid]);
            *(float4*)&g_hbuf[rd ^ 1][(j0 >> 2) * 256 + tid * 4] = vv;
            *(float4*)&out[((long long)tid * NT + t) * NH + j0] = vv;   // output[b][t][:]
            if (tail && t == NT - 1)
                *(float4*)&out[(long long)NB * NT * NH + tid * NH + j0] = vv;  // h_T
        }
        __syncthreads();

        // device-wide ticket barrier (monotonic counter: no reset, no gen race)
        if (tid == 0) {
            __threadfence();                               // release h writes
            unsigned arrive = atomicAdd(&g_cnt, 1);
            unsigned target = (arrive / GRID_R + 1) * GRID_R;
            const volatile unsigned* vc = (const volatile unsigned*)&g_cnt;
            while (*vc < target) {}
            __threadfence();                               // acquire peers' writes
        }
        __syncthreads();
        rd ^= 1;
    }

    if (tail) out[(long long)NB * NT * NH + NB * NH + b * NH + j] = cs;   // c_T
}

// ---------------- launch ----------------
extern "C" void kernel_launch(void* const* d_in, const int* in_sizes, int n_in,
                              void* d_out, int out_size) {
    const float* x   = (const float*)d_in[0];
    const float* h0  = (const float*)d_in[1];
    const float* c0  = (const float*)d_in[2];
    const float* Wih = (const float*)d_in[3];
    const float* Whh = (const float*)d_in[4];
    const float* bih = (const float*)d_in[5];
    const float* bhh = (const float*)d_in[6];
    float* out = (float*)d_out;

    init_kernel<<<128, 256>>>(h0, bih, bhh);
    gemm_xg<<<dim3(16, 256), 256>>>(x, Wih);
    int tail = (out_size >= NB * NT * NH + 2 * NB * NH) ? 1 : 0;
    lstm_steps<<<GRID_R, 256>>>(Whh, c0, out, tail);
}

// round 3
// speedup vs baseline: 1.1778x; 1.1778x over previous
#include <cuda_runtime.h>

#define NB 64
#define NT 512
#define NI 512
#define NH 512
#define NG 2048      // 4*H
#define GRID_R 128   // recurrent persistent CTAs

// ---------------- device scratch (static: no allocs allowed) ----------------
__device__ float g_xg[(long long)NT * NG * NB];   // [t][gate][b]  (256 MB)
__device__ float g_hbuf[2][NH * NB];              // [k/4][b][4] packed layout
__device__ unsigned g_grp[8 * 32];                // group counters, 128B apart
__device__ unsigned g_root;                       // root counter (monotonic)

// ---------------- f32x2 packed-FMA helpers (Blackwell FFMA2) ----------------
__device__ __forceinline__ unsigned long long dup2(float x) {
    unsigned long long r;
    asm("mov.b64 %0, {%1,%1};" : "=l"(r) : "f"(x));
    return r;
}
__device__ __forceinline__ void fma2(unsigned long long& d,
                                     unsigned long long a,
                                     unsigned long long b) {
    asm("fma.rn.f32x2 %0, %1, %2, %0;" : "+l"(d) : "l"(a), "l"(b));
}
__device__ __forceinline__ float2 unpack2(unsigned long long v) {
    float lo, hi;
    asm("mov.b64 {%0,%1}, %2;" : "=f"(lo), "=f"(hi) : "l"(v));
    return make_float2(lo, hi);
}

// ---------------- two-level grid barrier (monotonic, replay-safe) -----------
__device__ __forceinline__ void grid_bar(int tid) {
    __syncthreads();
    if (tid == 0) {
        __threadfence();                                   // release
        unsigned g = (blockIdx.x & 7) << 5;
        unsigned a = atomicAdd(&g_grp[g], 1u);
        unsigned epoch = a >> 4;                           // 16 CTAs/group
        if ((a & 15u) == 15u) atomicAdd(&g_root, 1u);      // last of group
        unsigned target = (epoch + 1u) * 8u;               // 8 groups/epoch
        const volatile unsigned* vr = (const volatile unsigned*)&g_root;
        while (*vr < target) {}
        __threadfence();                                   // acquire
    }
    __syncthreads();
}

// ---------------- xg GEMM: [32768,512] x [512,2048]^T -> g_xg[t][g][b] -------
#define STS_TILE(bufi)                                                         \
    do {                                                                       \
        As[bufi][ks + 0][r] = ra0.x; As[bufi][ks + 1][r] = ra0.y;              \
        As[bufi][ks + 2][r] = ra0.z; As[bufi][ks + 3][r] = ra0.w;              \
        As[bufi][ks + 4][r] = ra1.x; As[bufi][ks + 5][r] = ra1.y;              \
        As[bufi][ks + 6][r] = ra1.z; As[bufi][ks + 7][r] = ra1.w;              \
        Bs[bufi][ks + 0][r] = rb0.x; Bs[bufi][ks + 1][r] = rb0.y;              \
        Bs[bufi][ks + 2][r] = rb0.z; Bs[bufi][ks + 3][r] = rb0.w;              \
        Bs[bufi][ks + 4][r] = rb1.x; Bs[bufi][ks + 5][r] = rb1.y;              \
        Bs[bufi][ks + 6][r] = rb1.z; Bs[bufi][ks + 7][r] = rb1.w;              \
    } while (0)

__global__ __launch_bounds__(256, 2) void gemm_xg(const float* __restrict__ x,
                                                  const float* __restrict__ Wih,
                                                  const float* __restrict__ bih,
                                                  const float* __restrict__ bhh) {
    __shared__ __align__(16) float As[2][16][132];
    __shared__ __align__(16) float Bs[2][16][132];

    const int tid = threadIdx.x;
    const int n0 = blockIdx.x * 128;   // gate-column block (16 blocks)
    const int m0 = blockIdx.y * 128;   // row block (256 blocks)
    const int tm = tid >> 4;
    const int tn = tid & 15;
    const int r  = tid >> 1;           // tile row this thread stages
    const int ks = (tid & 1) * 8;      // k-segment within 16

    const float* pa = x   + (long long)(m0 + r) * NI + ks;
    const float* pb = Wih + (long long)(n0 + r) * NI + ks;

    unsigned long long acc[8][4];
#pragma unroll
    for (int i = 0; i < 8; ++i)
#pragma unroll
        for (int j = 0; j < 4; ++j) acc[i][j] = 0ull;

    float4 ra0, ra1, rb0, rb1;
    ra0 = *(const float4*)(pa);
    ra1 = *(const float4*)(pa + 4);
    rb0 = *(const float4*)(pb);
    rb1 = *(const float4*)(pb + 4);
    STS_TILE(0);
    __syncthreads();

#pragma unroll 1
    for (int kt = 0; kt < 32; ++kt) {
        const int buf = kt & 1;
        if (kt < 31) {
            const float* qa = pa + (kt + 1) * 16;
            const float* qb = pb + (kt + 1) * 16;
            ra0 = *(const float4*)(qa);
            ra1 = *(const float4*)(qa + 4);
            rb0 = *(const float4*)(qb);
            rb1 = *(const float4*)(qb + 4);
        }
#pragma unroll
        for (int kk = 0; kk < 16; ++kk) {
            float4 a0 = *(const float4*)&As[buf][kk][tm * 8];
            float4 a1 = *(const float4*)&As[buf][kk][tm * 8 + 4];
            ulonglong2 b01 = *(const ulonglong2*)&Bs[buf][kk][tn * 8];
            ulonglong2 b23 = *(const ulonglong2*)&Bs[buf][kk][tn * 8 + 4];
            float av[8] = {a0.x, a0.y, a0.z, a0.w, a1.x, a1.y, a1.z, a1.w};
            unsigned long long bp[4] = {b01.x, b01.y, b23.x, b23.y};
#pragma unroll
            for (int i = 0; i < 8; ++i) {
                unsigned long long ad = dup2(av[i]);
                fma2(acc[i][0], ad, bp[0]);
                fma2(acc[i][1], ad, bp[1]);
                fma2(acc[i][2], ad, bp[2]);
                fma2(acc[i][3], ad, bp[3]);
            }
        }
        if (kt < 31) {
            const int nb = buf ^ 1;
            STS_TILE(nb);
            __syncthreads();
        }
    }

    // Epilogue: +bias (read directly), write to g_xg[t][g][b]
    float bias_[8];
#pragma unroll
    for (int j = 0; j < 8; ++j) {
        int n = n0 + tn * 8 + j;
        bias_[j] = bih[n] + bhh[n];
    }
#pragma unroll
    for (int i = 0; i < 8; ++i) {
        int m  = m0 + tm * 8 + i;
        int bb = m >> 9;           // batch
        int t  = m & (NT - 1);     // timestep
        float* orow = g_xg + ((long long)t * NG + (n0 + tn * 8)) * NB + bb;
#pragma unroll
        for (int j2 = 0; j2 < 4; ++j2) {
            float2 v = unpack2(acc[i][j2]);
            orow[(2 * j2) * NB]     = v.x + bias_[2 * j2];
            orow[(2 * j2 + 1) * NB] = v.y + bias_[2 * j2 + 1];
        }
    }
}

// ---------------- persistent recurrent kernel (k-split by c) ----------------
// CTA owns H-columns [4*bid, 4*bid+4). Thread (b = tid&63, c = tid>>6)
// accumulates ALL 16 (gate,j) rows over k-quarter [c*128, c*128+128), then the
// 4 quarters are reduced through smem; thread (b,c) finalizes j-local = c.
__global__ __launch_bounds__(256, 1) void lstm_steps(const float* __restrict__ Whh,
                                                     const float* __restrict__ h0,
                                                     const float* __restrict__ c0,
                                                     float* __restrict__ out,
                                                     int tail) {
    // wsm2[k4][row] = W[q*NH + j0+cc][4k4..4k4+3], row = q*4+cc, 16B quads
    __shared__ __align__(16) float wsm2[128 * 16 * 4];   // 32 KB
    __shared__ __align__(16) float red[64][68];          // [b][r*4 + quarter]
    __shared__ float hx[256];

    const int tid = threadIdx.x;
    const int b   = tid & 63;
    const int c   = tid >> 6;
    const int j0  = blockIdx.x * 4;
    const int j   = j0 + c;

    // Stage W_hh slice (packed quads)
    for (int idx = tid; idx < 128 * 16; idx += 256) {
        int k4  = idx >> 4;
        int row = idx & 15;
        int q   = row >> 2;
        int cc  = row & 3;
        *(float4*)&wsm2[idx * 4] =
            *(const float4*)&Whh[(long long)(q * NH + j0 + cc) * NH + k4 * 4];
    }

    // Repack h0 slice: CTA bid owns k4 = bid (256 floats)
    {
        int bb = tid >> 2;
        int kk = tid & 3;
        g_hbuf[0][blockIdx.x * 256 + tid] = h0[bb * NH + blockIdx.x * 4 + kk];
    }

    float cs = c0[b * NH + j];
    int rd = 0;

    // prefetch xg for t = 0
    const float* xg0 = g_xg;
    float x0 = xg0[(0 * NH + j) * NB + b];
    float x1 = xg0[(1 * NH + j) * NB + b];
    float x2 = xg0[(2 * NH + j) * NB + b];
    float x3 = xg0[(3 * NH + j) * NB + b];

    grid_bar(tid);   // h0 repack visible everywhere (also covers wsm2 staging)

    const ulonglong2* wq = (const ulonglong2*)wsm2 + c * 32 * 16;

    for (int t = 0; t < NT; ++t) {
        // ---- partial matmul over this thread's k-quarter, all 16 rows ----
        const ulonglong2* hb2 =
            (const ulonglong2*)g_hbuf[rd] + (c * 32) * 64 + b;

        unsigned long long acc[16];
#pragma unroll
        for (int r2 = 0; r2 < 16; ++r2) acc[r2] = 0ull;

#pragma unroll 4
        for (int k4 = 0; k4 < 32; ++k4) {
            ulonglong2 h2 = hb2[k4 * 64];                 // h[b][4k..4k+3]
            const ulonglong2* wr = wq + (k4 << 4);
#pragma unroll
            for (int r2 = 0; r2 < 16; ++r2) {
                ulonglong2 w = wr[r2];
                fma2(acc[r2], h2.x, w.x);
                fma2(acc[r2], h2.y, w.y);
            }
        }

        // ---- reduce quarters through smem ----
#pragma unroll
        for (int r2 = 0; r2 < 16; ++r2) {
            float2 u = unpack2(acc[r2]);
            red[b][r2 * 4 + c] = (u.x + u.y);
        }
        __syncthreads();

        // thread (b,c) finalizes j-local = c: rows q*4+c
        float4 p0 = *(const float4*)&red[b][(0 * 4 + c) * 4];
        float4 p1 = *(const float4*)&red[b][(1 * 4 + c) * 4];
        float4 p2 = *(const float4*)&red[b][(2 * 4 + c) * 4];
        float4 p3 = *(const float4*)&red[b][(3 * 4 + c) * 4];
        float gi = (p0.x + p0.y) + (p0.z + p0.w) + x0;
        float gf = (p1.x + p1.y) + (p1.z + p1.w) + x1;
        float gg = (p2.x + p2.y) + (p2.z + p2.w) + x2;
        float go = (p3.x + p3.y) + (p3.z + p3.w) + x3;

        float iv = 1.f / (1.f + __expf(-gi));
        float fv = 1.f / (1.f + __expf(-gf));
        float gv = 2.f / (1.f + __expf(-2.f * gg)) - 1.f;
        float ov = 1.f / (1.f + __expf(-go));
        cs = fv * cs + iv * gv;
        float hn = ov * (2.f / (1.f + __expf(-2.f * cs)) - 1.f);

        // ---- smem exchange -> coalesced float4 stores of h and output ----
        hx[c * 64 + b] = hn;
        __syncthreads();
        if (tid < 64) {
            float4 vv = make_float4(hx[tid], hx[64 + tid], hx[128 + tid], hx[192 + tid]);
            *(float4*)&g_hbuf[rd ^ 1][blockIdx.x * 256 + tid * 4] = vv;
            *(float4*)&out[((long long)tid * NT + t) * NH + j0] = vv;   // output[b][t][:]
            if (tail && t == NT - 1)
                *(float4*)&out[(long long)NB * NT * NH + tid * NH + j0] = vv;  // h_T
        }

        // ---- prefetch next step's xg (h-independent) before the barrier ----
        int tn = (t + 1 < NT) ? t + 1 : t;
        const float* xgt = g_xg + (long long)tn * NG * NB;
        x0 = xgt[(0 * NH + j) * NB + b];
        x1 = xgt[(1 * NH + j) * NB + b];
        x2 = xgt[(2 * NH + j) * NB + b];
        x3 = xgt[(3 * NH + j) * NB + b];

        grid_bar(tid);
        rd ^= 1;
    }

    if (tail) out[(long long)NB * NT * NH + NB * NH + b * NH + j] = cs;   // c_T
}

// ---------------- launch ----------------
extern "C" void kernel_launch(void* const* d_in, const int* in_sizes, int n_in,
                              void* d_out, int out_size) {
    const float* x   = (const float*)d_in[0];
    const float* h0  = (const float*)d_in[1];
    const float* c0  = (const float*)d_in[2];
    const float* Wih = (const float*)d_in[3];
    const float* Whh = (const float*)d_in[4];
    const float* bih = (const float*)d_in[5];
    const float* bhh = (const float*)d_in[6];
    float* out = (float*)d_out;

    gemm_xg<<<dim3(16, 256), 256>>>(x, Wih, bih, bhh);
    int tail = (out_size >= NB * NT * NH + 2 * NB * NH) ? 1 : 0;
    lstm_steps<<<GRID_R, 256>>>(Whh, h0, c0, out, tail);
}

// round 4
// speedup vs baseline: 1.1888x; 1.0093x over previous
#include <cuda_runtime.h>

#define NB 64
#define NT 512
#define NI 512
#define NH 512
#define NG 2048      // 4*H
#define GRID_R 128   // recurrent persistent CTAs

// ---------------- device scratch (static: no allocs allowed) ----------------
__device__ float g_xg[(long long)NT * NG * NB];   // [t][gate][b]  (256 MB)
__device__ float g_hbuf[2][NH * NB];              // [k/4][b][4] packed layout
__device__ unsigned g_grp[8 * 32];                // group counters, 128B apart
__device__ unsigned g_root;                       // root counter (monotonic)

// ---------------- f32x2 packed-FMA helpers (Blackwell FFMA2) ----------------
__device__ __forceinline__ unsigned long long dup2(float x) {
    unsigned long long r;
    asm("mov.b64 %0, {%1,%1};" : "=l"(r) : "f"(x));
    return r;
}
__device__ __forceinline__ void fma2(unsigned long long& d,
                                     unsigned long long a,
                                     unsigned long long b) {
    asm("fma.rn.f32x2 %0, %1, %2, %0;" : "+l"(d) : "l"(a), "l"(b));
}
__device__ __forceinline__ float2 unpack2(unsigned long long v) {
    float lo, hi;
    asm("mov.b64 {%0,%1}, %2;" : "=f"(lo), "=f"(hi) : "l"(v));
    return make_float2(lo, hi);
}

// ---------------- two-level grid barrier (monotonic, replay-safe) -----------
__device__ __forceinline__ void grid_bar(int tid) {
    __syncthreads();
    if (tid == 0) {
        __threadfence();                                   // release
        unsigned g = (blockIdx.x & 7) << 5;
        unsigned a = atomicAdd(&g_grp[g], 1u);
        unsigned epoch = a >> 4;                           // 16 CTAs/group
        if ((a & 15u) == 15u) atomicAdd(&g_root, 1u);      // last of group
        unsigned target = (epoch + 1u) * 8u;               // 8 groups/epoch
        const volatile unsigned* vr = (const volatile unsigned*)&g_root;
        while (*vr < target) {}
        __threadfence();                                   // acquire
    }
    __syncthreads();
}

// ---------------- xg GEMM: [32768,512] x [512,2048]^T -> g_xg[t][g][b] -------
#define STS_TILE(bufi)                                                         \
    do {                                                                       \
        As[bufi][ks + 0][r] = ra0.x; As[bufi][ks + 1][r] = ra0.y;              \
        As[bufi][ks + 2][r] = ra0.z; As[bufi][ks + 3][r] = ra0.w;              \
        As[bufi][ks + 4][r] = ra1.x; As[bufi][ks + 5][r] = ra1.y;              \
        As[bufi][ks + 6][r] = ra1.z; As[bufi][ks + 7][r] = ra1.w;              \
        Bs[bufi][ks + 0][r] = rb0.x; Bs[bufi][ks + 1][r] = rb0.y;              \
        Bs[bufi][ks + 2][r] = rb0.z; Bs[bufi][ks + 3][r] = rb0.w;              \
        Bs[bufi][ks + 4][r] = rb1.x; Bs[bufi][ks + 5][r] = rb1.y;              \
        Bs[bufi][ks + 6][r] = rb1.z; Bs[bufi][ks + 7][r] = rb1.w;              \
    } while (0)

__global__ __launch_bounds__(256, 2) void gemm_xg(const float* __restrict__ x,
                                                  const float* __restrict__ Wih,
                                                  const float* __restrict__ bih,
                                                  const float* __restrict__ bhh) {
    __shared__ __align__(16) float As[2][16][132];
    __shared__ __align__(16) float Bs[2][16][132];

    const int tid = threadIdx.x;
    const int n0 = blockIdx.x * 128;   // gate-column block (16 blocks)
    const int m0 = blockIdx.y * 128;   // row block (256 blocks)
    const int tm = tid >> 4;
    const int tn = tid & 15;
    const int r  = tid >> 1;           // tile row this thread stages
    const int ks = (tid & 1) * 8;      // k-segment within 16

    const float* pa = x   + (long long)(m0 + r) * NI + ks;
    const float* pb = Wih + (long long)(n0 + r) * NI + ks;

    unsigned long long acc[8][4];
#pragma unroll
    for (int i = 0; i < 8; ++i)
#pragma unroll
        for (int j = 0; j < 4; ++j) acc[i][j] = 0ull;

    float4 ra0, ra1, rb0, rb1;
    ra0 = *(const float4*)(pa);
    ra1 = *(const float4*)(pa + 4);
    rb0 = *(const float4*)(pb);
    rb1 = *(const float4*)(pb + 4);
    STS_TILE(0);
    __syncthreads();

#pragma unroll 1
    for (int kt = 0; kt < 32; ++kt) {
        const int buf = kt & 1;
        if (kt < 31) {
            const float* qa = pa + (kt + 1) * 16;
            const float* qb = pb + (kt + 1) * 16;
            ra0 = *(const float4*)(qa);
            ra1 = *(const float4*)(qa + 4);
            rb0 = *(const float4*)(qb);
            rb1 = *(const float4*)(qb + 4);
        }
#pragma unroll
        for (int kk = 0; kk < 16; ++kk) {
            float4 a0 = *(const float4*)&As[buf][kk][tm * 8];
            float4 a1 = *(const float4*)&As[buf][kk][tm * 8 + 4];
            ulonglong2 b01 = *(const ulonglong2*)&Bs[buf][kk][tn * 8];
            ulonglong2 b23 = *(const ulonglong2*)&Bs[buf][kk][tn * 8 + 4];
            float av[8] = {a0.x, a0.y, a0.z, a0.w, a1.x, a1.y, a1.z, a1.w};
            unsigned long long bp[4] = {b01.x, b01.y, b23.x, b23.y};
#pragma unroll
            for (int i = 0; i < 8; ++i) {
                unsigned long long ad = dup2(av[i]);
                fma2(acc[i][0], ad, bp[0]);
                fma2(acc[i][1], ad, bp[1]);
                fma2(acc[i][2], ad, bp[2]);
                fma2(acc[i][3], ad, bp[3]);
            }
        }
        if (kt < 31) {
            const int nb = buf ^ 1;
            STS_TILE(nb);
            __syncthreads();
        }
    }

    // Epilogue: +bias, write to g_xg[t][g][b]
    float bias_[8];
#pragma unroll
    for (int j = 0; j < 8; ++j) {
        int n = n0 + tn * 8 + j;
        bias_[j] = bih[n] + bhh[n];
    }
#pragma unroll
    for (int i = 0; i < 8; ++i) {
        int m  = m0 + tm * 8 + i;
        int bb = m >> 9;           // batch
        int t  = m & (NT - 1);     // timestep
        float* orow = g_xg + ((long long)t * NG + (n0 + tn * 8)) * NB + bb;
#pragma unroll
        for (int j2 = 0; j2 < 4; ++j2) {
            float2 v = unpack2(acc[i][j2]);
            orow[(2 * j2) * NB]     = v.x + bias_[2 * j2];
            orow[(2 * j2 + 1) * NB] = v.y + bias_[2 * j2 + 1];
        }
    }
}

// ---------------- persistent recurrent kernel (8-way k-split) ----------------
// CTA owns H-columns [4*bid, 4*bid+4). Thread (b = tid&63, c = tid>>6, c<8)
// accumulates ALL 16 (gate,j) rows over k-slice [c*64, c*64+64); the 8
// partials per (row,b) are reduced through smem; thread (b,c<4) finalizes j=c.
__global__ __launch_bounds__(512, 1) void lstm_steps(const float* __restrict__ Whh,
                                                     const float* __restrict__ h0,
                                                     const float* __restrict__ c0,
                                                     float* __restrict__ out,
                                                     int tail) {
    // wsm2[k4][row] = W[q*NH + j0+cc][4k4..4k4+3], row = q*4+cc, 16B quads
    __shared__ __align__(16) float wsm2[128 * 16 * 4];   // 32 KB
    __shared__ __align__(16) float red2[16 * 8 * 64];    // [row][c][b]  32 KB
    __shared__ float hx[256];

    const int tid = threadIdx.x;
    const int b   = tid & 63;
    const int c   = tid >> 6;          // 0..7
    const int j0  = blockIdx.x * 4;
    const int j   = j0 + (c & 3);

    // Stage W_hh slice (packed quads)
    for (int idx = tid; idx < 128 * 16; idx += 512) {
        int k4  = idx >> 4;
        int row = idx & 15;
        int q   = row >> 2;
        int cc  = row & 3;
        *(float4*)&wsm2[idx * 4] =
            *(const float4*)&Whh[(long long)(q * NH + j0 + cc) * NH + k4 * 4];
    }

    // Repack h0 slice: CTA bid owns k4 = bid (256 floats)
    if (tid < 256) {
        int bb = tid >> 2;
        int kk = tid & 3;
        g_hbuf[0][blockIdx.x * 256 + tid] = h0[bb * NH + blockIdx.x * 4 + kk];
    }

    float cs = (c < 4) ? c0[b * NH + j] : 0.f;
    int rd = 0;

    // prefetch xg for t = 0 (only finalizing threads need it)
    float x0 = 0.f, x1 = 0.f, x2 = 0.f, x3 = 0.f;
    if (c < 4) {
        x0 = g_xg[(0 * NH + j) * NB + b];
        x1 = g_xg[(1 * NH + j) * NB + b];
        x2 = g_xg[(2 * NH + j) * NB + b];
        x3 = g_xg[(3 * NH + j) * NB + b];
    }

    grid_bar(tid);   // h0 repack visible everywhere (also covers wsm2 staging)

    const ulonglong2* wq = (const ulonglong2*)wsm2 + (c * 16) * 16;

    for (int t = 0; t < NT; ++t) {
        // ---- partial matmul over this thread's k-slice, all 16 rows ----
        const ulonglong2* hb2 =
            (const ulonglong2*)g_hbuf[rd] + (c * 16) * 64 + b;

        unsigned long long acc[16];
#pragma unroll
        for (int r2 = 0; r2 < 16; ++r2) acc[r2] = 0ull;

#pragma unroll 4
        for (int k4 = 0; k4 < 16; ++k4) {
            ulonglong2 h2 = hb2[k4 * 64];                 // h[b][4k..4k+3]
            const ulonglong2* wr = wq + (k4 << 4);
#pragma unroll
            for (int r2 = 0; r2 < 16; ++r2) {
                ulonglong2 w = wr[r2];
                fma2(acc[r2], h2.x, w.x);
                fma2(acc[r2], h2.y, w.y);
            }
        }

        // ---- write partials: red2[row][c][b] (lanes=b contiguous: no conflicts)
#pragma unroll
        for (int r2 = 0; r2 < 16; ++r2) {
            float2 u = unpack2(acc[r2]);
            red2[(r2 << 9) + (c << 6) + b] = u.x + u.y;
        }
        __syncthreads();

        float hn = 0.f;
        if (c < 4) {
            // finalize j-local = c: rows q*4+c, summing the 8 k-partials
            float g4[4];
#pragma unroll
            for (int q = 0; q < 4; ++q) {
                const float* rp = &red2[((q * 4 + c) << 9) + b];
                float s = 0.f;
#pragma unroll
                for (int cc = 0; cc < 8; ++cc) s += rp[cc << 6];
                g4[q] = s;
            }
            float gi = g4[0] + x0;
            float gf = g4[1] + x1;
            float gg = g4[2] + x2;
            float go = g4[3] + x3;

            float iv = 1.f / (1.f + __expf(-gi));
            float fv = 1.f / (1.f + __expf(-gf));
            float gv = 2.f / (1.f + __expf(-2.f * gg)) - 1.f;
            float ov = 1.f / (1.f + __expf(-go));
            cs = fv * cs + iv * gv;
            hn = ov * (2.f / (1.f + __expf(-2.f * cs)) - 1.f);
        }
        __syncthreads();              // red2 consumed before next-step reuse
        if (c < 4) hx[c * 64 + b] = hn;
        __syncthreads();
        if (tid < 64) {
            float4 vv = make_float4(hx[tid], hx[64 + tid], hx[128 + tid], hx[192 + tid]);
            *(float4*)&g_hbuf[rd ^ 1][blockIdx.x * 256 + tid * 4] = vv;
            *(float4*)&out[((long long)tid * NT + t) * NH + j0] = vv;   // output[b][t][:]
            if (tail && t == NT - 1)
                *(float4*)&out[(long long)NB * NT * NH + tid * NH + j0] = vv;  // h_T
        }

        // ---- prefetch next step's xg (h-independent) before the barrier ----
        if (c < 4) {
            int tn2 = (t + 1 < NT) ? t + 1 : t;
            const float* xgt = g_xg + (long long)tn2 * NG * NB;
            x0 = xgt[(0 * NH + j) * NB + b];
            x1 = xgt[(1 * NH + j) * NB + b];
            x2 = xgt[(2 * NH + j) * NB + b];
            x3 = xgt[(3 * NH + j) * NB + b];
        }

        grid_bar(tid);
        rd ^= 1;
    }

    if (tail && c < 4) out[(long long)NB * NT * NH + NB * NH + b * NH + j] = cs;  // c_T
}

// ---------------- launch ----------------
extern "C" void kernel_launch(void* const* d_in, const int* in_sizes, int n_in,
                              void* d_out, int out_size) {
    const float* x   = (const float*)d_in[0];
    const float* h0  = (const float*)d_in[1];
    const float* c0  = (const float*)d_in[2];
    const float* Wih = (const float*)d_in[3];
    const float* Whh = (const float*)d_in[4];
    const float* bih = (const float*)d_in[5];
    const float* bhh = (const float*)d_in[6];
    float* out = (float*)d_out;

    gemm_xg<<<dim3(16, 256), 256>>>(x, Wih, bih, bhh);
    int tail = (out_size >= NB * NT * NH + 2 * NB * NH) ? 1 : 0;
    lstm_steps<<<GRID_R, 512>>>(Whh, h0, c0, out, tail);
}

// round 5
// speedup vs baseline: 1.3239x; 1.1137x over previous
#include <cuda_runtime.h>

#define NB 64
#define NT 512
#define NI 512
#define NH 512
#define NG 2048      // 4*H
#define GRID_R 128   // recurrent persistent CTAs

// ---------------- device scratch (static: no allocs allowed) ----------------
__device__ float g_xg[(long long)NT * NG * NB];   // [t][gate][b]  (256 MB)
__device__ float g_hbuf[2][NH * NB];              // [k/4][b][4] packed layout
__device__ unsigned g_grp[8 * 32];                // group counters, 128B apart
__device__ unsigned g_root;                       // root counter (monotonic)

// ---------------- f32x2 packed-FMA helpers (Blackwell FFMA2) ----------------
__device__ __forceinline__ unsigned long long dup2(float x) {
    unsigned long long r;
    asm("mov.b64 %0, {%1,%1};" : "=l"(r) : "f"(x));
    return r;
}
__device__ __forceinline__ void fma2(unsigned long long& d,
                                     unsigned long long a,
                                     unsigned long long b) {
    asm("fma.rn.f32x2 %0, %1, %2, %0;" : "+l"(d) : "l"(a), "l"(b));
}
__device__ __forceinline__ float2 unpack2(unsigned long long v) {
    float lo, hi;
    asm("mov.b64 {%0,%1}, %2;" : "=f"(lo), "=f"(hi) : "l"(v));
    return make_float2(lo, hi);
}

// ---------------- two-level grid barrier (monotonic, replay-safe) -----------
__device__ __forceinline__ void grid_bar(int tid) {
    __syncthreads();
    if (tid == 0) {
        __threadfence();                                   // release
        unsigned g = (blockIdx.x & 7) << 5;
        unsigned a = atomicAdd(&g_grp[g], 1u);
        unsigned epoch = a >> 4;                           // 16 CTAs/group
        if ((a & 15u) == 15u) atomicAdd(&g_root, 1u);      // last of group
        unsigned target = (epoch + 1u) * 8u;               // 8 groups/epoch
        const volatile unsigned* vr = (const volatile unsigned*)&g_root;
        while (*vr < target) {}
        __threadfence();                                   // acquire
    }
    __syncthreads();
}

// ---------------- xg GEMM: [32768,512] x [512,2048]^T -> g_xg[t][g][b] -------
#define STS_TILE(bufi)                                                         \
    do {                                                                       \
        As[bufi][ks + 0][r] = ra0.x; As[bufi][ks + 1][r] = ra0.y;              \
        As[bufi][ks + 2][r] = ra0.z; As[bufi][ks + 3][r] = ra0.w;              \
        As[bufi][ks + 4][r] = ra1.x; As[bufi][ks + 5][r] = ra1.y;              \
        As[bufi][ks + 6][r] = ra1.z; As[bufi][ks + 7][r] = ra1.w;              \
        Bs[bufi][ks + 0][r] = rb0.x; Bs[bufi][ks + 1][r] = rb0.y;              \
        Bs[bufi][ks + 2][r] = rb0.z; Bs[bufi][ks + 3][r] = rb0.w;              \
        Bs[bufi][ks + 4][r] = rb1.x; Bs[bufi][ks + 5][r] = rb1.y;              \
        Bs[bufi][ks + 6][r] = rb1.z; Bs[bufi][ks + 7][r] = rb1.w;              \
    } while (0)

__global__ __launch_bounds__(256, 2) void gemm_xg(const float* __restrict__ x,
                                                  const float* __restrict__ Wih,
                                                  const float* __restrict__ bih,
                                                  const float* __restrict__ bhh) {
    __shared__ __align__(16) float As[2][16][132];
    __shared__ __align__(16) float Bs[2][16][132];

    const int tid = threadIdx.x;
    const int n0 = blockIdx.x * 128;   // gate-column block (16 blocks)
    const int m0 = blockIdx.y * 128;   // row block (256 blocks)
    const int tm = tid >> 4;
    const int tn = tid & 15;
    const int r  = tid >> 1;           // tile row this thread stages
    const int ks = (tid & 1) * 8;      // k-segment within 16

    const float* pa = x   + (long long)(m0 + r) * NI + ks;
    const float* pb = Wih + (long long)(n0 + r) * NI + ks;

    unsigned long long acc[8][4];
#pragma unroll
    for (int i = 0; i < 8; ++i)
#pragma unroll
        for (int j = 0; j < 4; ++j) acc[i][j] = 0ull;

    float4 ra0, ra1, rb0, rb1;
    ra0 = *(const float4*)(pa);
    ra1 = *(const float4*)(pa + 4);
    rb0 = *(const float4*)(pb);
    rb1 = *(const float4*)(pb + 4);
    STS_TILE(0);
    __syncthreads();

#pragma unroll 1
    for (int kt = 0; kt < 32; ++kt) {
        const int buf = kt & 1;
        if (kt < 31) {
            const float* qa = pa + (kt + 1) * 16;
            const float* qb = pb + (kt + 1) * 16;
            ra0 = *(const float4*)(qa);
            ra1 = *(const float4*)(qa + 4);
            rb0 = *(const float4*)(qb);
            rb1 = *(const float4*)(qb + 4);
        }
#pragma unroll
        for (int kk = 0; kk < 16; ++kk) {
            float4 a0 = *(const float4*)&As[buf][kk][tm * 8];
            float4 a1 = *(const float4*)&As[buf][kk][tm * 8 + 4];
            ulonglong2 b01 = *(const ulonglong2*)&Bs[buf][kk][tn * 8];
            ulonglong2 b23 = *(const ulonglong2*)&Bs[buf][kk][tn * 8 + 4];
            float av[8] = {a0.x, a0.y, a0.z, a0.w, a1.x, a1.y, a1.z, a1.w};
            unsigned long long bp[4] = {b01.x, b01.y, b23.x, b23.y};
#pragma unroll
            for (int i = 0; i < 8; ++i) {
                unsigned long long ad = dup2(av[i]);
                fma2(acc[i][0], ad, bp[0]);
                fma2(acc[i][1], ad, bp[1]);
                fma2(acc[i][2], ad, bp[2]);
                fma2(acc[i][3], ad, bp[3]);
            }
        }
        if (kt < 31) {
            const int nb = buf ^ 1;
            STS_TILE(nb);
            __syncthreads();
        }
    }

    // Epilogue: +bias, write to g_xg[t][g][b]
    float bias_[8];
#pragma unroll
    for (int j = 0; j < 8; ++j) {
        int n = n0 + tn * 8 + j;
        bias_[j] = bih[n] + bhh[n];
    }
#pragma unroll
    for (int i = 0; i < 8; ++i) {
        int m  = m0 + tm * 8 + i;
        int bb = m >> 9;           // batch
        int t  = m & (NT - 1);     // timestep
        float* orow = g_xg + ((long long)t * NG + (n0 + tn * 8)) * NB + bb;
#pragma unroll
        for (int j2 = 0; j2 < 4; ++j2) {
            float2 v = unpack2(acc[i][j2]);
            orow[(2 * j2) * NB]     = v.x + bias_[2 * j2];
            orow[(2 * j2 + 1) * NB] = v.y + bias_[2 * j2 + 1];
        }
    }
}

// ---------------- persistent recurrent kernel ------------------------------
// CTA owns H-columns [4*bid, 4*bid+4). 512 threads = 16 warps; warp w = k-slice
// [w*32, w*32+32). Each thread covers 2 batch elems (b0, b0+32), all 16
// (gate,j) rows: one W LDS feeds 4 FFMA2. Partials (16 c-slices) reduced via
// smem in two row-halves; threads tid<256 (fb=tid&63, fj=(tid>>6)&3) finalize.
__global__ __launch_bounds__(512, 1) void lstm_steps(const float* __restrict__ Whh,
                                                     const float* __restrict__ h0,
                                                     const float* __restrict__ c0,
                                                     float* __restrict__ out,
                                                     int tail) {
    // wsm2 quad (k4*16 + row) = W[q*NH + j0+cc][4k4..4k4+3], row = q*4+cc
    __shared__ __align__(16) float wsm2[128 * 16 * 4];   // 32 KB
    __shared__ __align__(16) float red2[8 * 16 * 64];    // 32 KB [rowHalf][c][b]
    __shared__ float hx[256];

    const int tid = threadIdx.x;
    const int b0  = tid & 31;
    const int c   = tid >> 5;          // warp id = k-slice 0..15
    const int fb  = tid & 63;          // finalize batch
    const int fj  = (tid >> 6) & 3;    // finalize j-local
    const int j0  = blockIdx.x * 4;
    const int jf  = j0 + fj;

    // Stage W_hh slice (packed quads)
    for (int idx = tid; idx < 128 * 16; idx += 512) {
        int k4  = idx >> 4;
        int row = idx & 15;
        int q   = row >> 2;
        int cc  = row & 3;
        *(float4*)&wsm2[idx * 4] =
            *(const float4*)&Whh[(long long)(q * NH + j0 + cc) * NH + k4 * 4];
    }

    // Repack h0 slice: CTA bid owns k4 = bid (256 floats)
    if (tid < 256) {
        int bb = tid >> 2;
        int kk = tid & 3;
        g_hbuf[0][blockIdx.x * 256 + tid] = h0[bb * NH + blockIdx.x * 4 + kk];
    }

    float cs = 0.f, x0 = 0.f, x1 = 0.f, x2 = 0.f, x3 = 0.f;
    if (tid < 256) {
        cs = c0[fb * NH + jf];
        x0 = g_xg[(0 * NH + jf) * NB + fb];
        x1 = g_xg[(1 * NH + jf) * NB + fb];
        x2 = g_xg[(2 * NH + jf) * NB + fb];
        x3 = g_xg[(3 * NH + jf) * NB + fb];
    }
    int rd = 0;

    grid_bar(tid);   // h0 repack + wsm2 staging visible

    const int kbase = c * 8;                       // k4 base for this warp
    const ulonglong2* wq = (const ulonglong2*)wsm2 + (kbase << 4);

    for (int t = 0; t < NT; ++t) {
        const ulonglong2* hb2 = (const ulonglong2*)g_hbuf[rd];

        unsigned long long acc[16][2];
#pragma unroll
        for (int r2 = 0; r2 < 16; ++r2) { acc[r2][0] = 0ull; acc[r2][1] = 0ull; }

        ulonglong2 ha = hb2[kbase * 64 + b0];
        ulonglong2 hc = hb2[kbase * 64 + b0 + 32];
#pragma unroll
        for (int k4 = 0; k4 < 8; ++k4) {
            ulonglong2 hA = ha, hB = hc;
            if (k4 < 7) {                           // depth-1 prefetch next k4
                ha = hb2[(kbase + k4 + 1) * 64 + b0];
                hc = hb2[(kbase + k4 + 1) * 64 + b0 + 32];
            }
            const ulonglong2* wr = wq + (k4 << 4);
#pragma unroll
            for (int r2 = 0; r2 < 16; ++r2) {
                ulonglong2 w = wr[r2];              // one LDS feeds 4 FFMA2
                fma2(acc[r2][0], hA.x, w.x);
                fma2(acc[r2][0], hA.y, w.y);
                fma2(acc[r2][1], hB.x, w.x);
                fma2(acc[r2][1], hB.y, w.y);
            }
        }

        // ---- half 1: rows 0..7 (gates i, f) ----
#pragma unroll
        for (int r2 = 0; r2 < 8; ++r2) {
            float2 u0 = unpack2(acc[r2][0]);
            float2 u1 = unpack2(acc[r2][1]);
            red2[(r2 << 10) + (c << 6) + b0]      = u0.x + u0.y;
            red2[(r2 << 10) + (c << 6) + b0 + 32] = u1.x + u1.y;
        }
        __syncthreads();
        float gi = x0, gf = x1;
        if (tid < 256) {
            const float* p0 = &red2[((0 * 4 + fj) << 10) + fb];
            const float* p1 = &red2[((1 * 4 + fj) << 10) + fb];
#pragma unroll
            for (int cc = 0; cc < 16; ++cc) {
                gi += p0[cc << 6];
                gf += p1[cc << 6];
            }
        }
        __syncthreads();
        // ---- half 2: rows 8..15 (gates g, o) ----
#pragma unroll
        for (int r2 = 8; r2 < 16; ++r2) {
            float2 u0 = unpack2(acc[r2][0]);
            float2 u1 = unpack2(acc[r2][1]);
            red2[((r2 - 8) << 10) + (c << 6) + b0]      = u0.x + u0.y;
            red2[((r2 - 8) << 10) + (c << 6) + b0 + 32] = u1.x + u1.y;
        }
        __syncthreads();
        if (tid < 256) {
            float gg = x2, go = x3;
            const float* p2 = &red2[((0 * 4 + fj) << 10) + fb];
            const float* p3 = &red2[((1 * 4 + fj) << 10) + fb];
#pragma unroll
            for (int cc = 0; cc < 16; ++cc) {
                gg += p2[cc << 6];
                go += p3[cc << 6];
            }
            float iv = 1.f / (1.f + __expf(-gi));
            float fv = 1.f / (1.f + __expf(-gf));
            float gv = 2.f / (1.f + __expf(-2.f * gg)) - 1.f;
            float ov = 1.f / (1.f + __expf(-go));
            cs = fv * cs + iv * gv;
            float hn = ov * (2.f / (1.f + __expf(-2.f * cs)) - 1.f);
            hx[fj * 64 + fb] = hn;
        }
        __syncthreads();
        if (tid < 64) {
            float4 vv = make_float4(hx[tid], hx[64 + tid], hx[128 + tid], hx[192 + tid]);
            *(float4*)&g_hbuf[rd ^ 1][blockIdx.x * 256 + tid * 4] = vv;
            *(float4*)&out[((long long)tid * NT + t) * NH + j0] = vv;   // output[b][t][:]
            if (tail && t == NT - 1)
                *(float4*)&out[(long long)NB * NT * NH + tid * NH + j0] = vv;  // h_T
        }

        // prefetch next step's xg (h-independent) before the barrier
        if (tid < 256) {
            int tn2 = (t + 1 < NT) ? t + 1 : t;
            const float* xgt = g_xg + (long long)tn2 * NG * NB;
            x0 = xgt[(0 * NH + jf) * NB + fb];
            x1 = xgt[(1 * NH + jf) * NB + fb];
            x2 = xgt[(2 * NH + jf) * NB + fb];
            x3 = xgt[(3 * NH + jf) * NB + fb];
        }

        grid_bar(tid);
        rd ^= 1;
    }

    if (tail && tid < 256)
        out[(long long)NB * NT * NH + NB * NH + fb * NH + jf] = cs;   // c_T
}

// ---------------- launch ----------------
extern "C" void kernel_launch(void* const* d_in, const int* in_sizes, int n_in,
                              void* d_out, int out_size) {
    const float* x   = (const float*)d_in[0];
    const float* h0  = (const float*)d_in[1];
    const float* c0  = (const float*)d_in[2];
    const float* Wih = (const float*)d_in[3];
    const float* Whh = (const float*)d_in[4];
    const float* bih = (const float*)d_in[5];
    const float* bhh = (const float*)d_in[6];
    float* out = (float*)d_out;

    gemm_xg<<<dim3(16, 256), 256>>>(x, Wih, bih, bhh);
    int tail = (out_size >= NB * NT * NH + 2 * NB * NH) ? 1 : 0;
    lstm_steps<<<GRID_R, 512>>>(Whh, h0, c0, out, tail);
}